// round 16
// baseline (speedup 1.0000x reference)
#include <cuda_runtime.h>
#include <cuda_bf16.h>
#include <math.h>
#include <stdint.h>

// ---------------- problem constants ----------------
#define BSZ   4
#define TT    64
#define NNODE 128
#define NF    16
#define HID   64
#define HEADS 4
#define RH    256
#define LD    64
#define EPG   1024
#define NG    (BSZ*TT)        // 256 graphs
#define NTOT  (NG*NNODE)      // 32768 nodes
#define MD    64              // adjacency capacity in g_adj
#define MD2   32              // capacity used by fused agg (actual deg ~9-20)

// ---------------- device scratch ----------------
__device__ float g_bufA[NTOT*256];           // 32 MB
__device__ float g_bufB[NTOT*256];           // 32 MB
__device__ int   g_adj[NNODE*MD];
__device__ int   g_deg[NNODE];
__device__ float g_embs[NG*HID];             // graph embeddings
__device__ float g_gx[2*TT*BSZ*1024];        // precomputed x@Wih^T + biases
__device__ float g_hT[2*BSZ*RH];             // final hidden states

// ---------------- small PTX helpers ----------------
__device__ __forceinline__ uint32_t smem_u32(const void* p) {
    uint32_t a;
    asm("{ .reg .u64 t; cvta.to.shared.u64 t, %1; cvt.u32.u64 %0, t; }" : "=r"(a) : "l"(p));
    return a;
}
__device__ __forceinline__ void st_cluster_f32(uint32_t laddr, uint32_t rank, float v) {
    uint32_t ra;
    asm volatile("mapa.shared::cluster.u32 %0, %1, %2;" : "=r"(ra) : "r"(laddr), "r"(rank));
    asm volatile("st.shared::cluster.f32 [%0], %1;" :: "r"(ra), "f"(v) : "memory");
}
__device__ __forceinline__ void mma_bf16(float* c, const uint32_t* a, const uint32_t* b) {
    asm volatile(
        "mma.sync.aligned.m16n8k16.row.col.f32.bf16.bf16.f32 "
        "{%0,%1,%2,%3}, {%4,%5,%6,%7}, {%8,%9}, {%0,%1,%2,%3};"
        : "+f"(c[0]), "+f"(c[1]), "+f"(c[2]), "+f"(c[3])
        : "r"(a[0]), "r"(a[1]), "r"(a[2]), "r"(a[3]), "r"(b[0]), "r"(b[1]));
}
__device__ __forceinline__ void ldsm4(uint32_t* r, uint32_t addr) {
    asm volatile("ldmatrix.sync.aligned.m8n8.x4.shared.b16 {%0,%1,%2,%3}, [%4];"
        : "=r"(r[0]), "=r"(r[1]), "=r"(r[2]), "=r"(r[3]) : "r"(addr));
}
#define MBARRIER_INIT(addr, cnt) \
    asm volatile("mbarrier.init.shared.b64 [%0], %1;" :: "r"((uint32_t)(addr)), "r"((uint32_t)(cnt)) : "memory")
// remote arrive with release semantics at cluster scope (orders this thread's
// prior st.shared::cluster stores before the arrival becomes visible)
#define MBAR_ARRIVE_REL_CLUSTER(local_mbar, trank) \
    asm volatile("{\n\t.reg .b32 ra;\n\t" \
                 "mapa.shared::cluster.u32 ra, %0, %1;\n\t" \
                 "mbarrier.arrive.release.cluster.shared::cluster.b64 _, [ra];\n\t}" \
                 :: "r"((uint32_t)(local_mbar)), "r"((uint32_t)(trank)) : "memory")
#define MBAR_WAIT_CLUSTER(mbar_addr, parity) do { \
    uint32_t _m = (uint32_t)(mbar_addr); \
    uint32_t _p = (uint32_t)(parity); \
    uint32_t _d; \
    asm volatile("{\n\t.reg .pred p;\n\t" \
        "mbarrier.try_wait.parity.acquire.cluster.shared::cta.b64 p, [%1], %2;\n\t" \
        "selp.b32 %0, 1, 0, p;\n\t}" : "=r"(_d) : "r"(_m), "r"(_p) : "memory"); \
    if (!_d) { \
        asm volatile("{\n\t.reg .pred P1;\n\t" \
            "WL_%=:\n\t" \
            "mbarrier.try_wait.parity.acquire.cluster.shared::cta.b64 P1, [%0], %1, 0x989680;\n\t" \
            "@P1 bra.uni WD_%=;\n\t" \
            "bra.uni WL_%=;\n\t" \
            "WD_%=:\n\t}" :: "r"(_m), "r"(_p) : "memory"); \
    } \
} while(0)

// ---------------- CSR build (deterministic, parallel prefix) ----------------
__global__ __launch_bounds__(1024) void build_adj_kernel(const int* __restrict__ ei) {
    __shared__ int ss[EPG];
    __shared__ int sd[EPG];
    __shared__ int cnts[8][NNODE];
    int tid = threadIdx.x;
    for (int e = tid; e < EPG; e += 1024) { ss[e] = ei[e]; sd[e] = ei[EPG + e]; }
    __syncthreads();
    int d = tid & 127, seg = tid >> 7;       // 8 segments x 128 dst
    int e0 = seg * 128;
    int cnt = 0;
    for (int e = e0; e < e0 + 128; e++) cnt += (sd[e] == d);
    cnts[seg][d] = cnt;
    __syncthreads();
    int o = 0;
    for (int s2 = 0; s2 < seg; s2++) o += cnts[s2][d];
    for (int e = e0; e < e0 + 128; e++) {
        if (sd[e] == d && o < MD-1) g_adj[d*MD + o++] = ss[e];
    }
    if (seg == 7) {                          // last segment appends self loop
        g_adj[d*MD + o] = d;
        g_deg[d] = o + 1;
    }
}

// ---------------- HMMA bf16x3 GEMM, double-buffered pipeline ---------------
template<int NFULL, int BN>
__global__ __launch_bounds__(256) void hmma_gemm(
    const float* __restrict__ A, const float* __restrict__ W,
    float* __restrict__ C, int K)
{
    constexpr int KC = 32;
    constexpr int KP = 40;
    constexpr int NT8 = BN/8;
    constexpr int NB  = BN/16;               // B float-pairs per thread
    extern __shared__ __align__(16) __nv_bfloat16 gsm[];
    constexpr int APL = 128*KP;              // A plane elems
    constexpr int BPL = BN*KP;               // B plane elems
    constexpr int BBASE = 4*APL;

    int tid = threadIdx.x;
    int wid = tid >> 5, lane = tid & 31;
    int bm0 = blockIdx.x * 128;
    int bn0 = blockIdx.y * BN;
    int r0 = wid * 16;

    float acc[NT8][4];
    #pragma unroll
    for (int t = 0; t < NT8; t++)
        #pragma unroll
        for (int i = 0; i < 4; i++) acc[t][i] = 0.f;

    uint32_t sm0 = smem_u32(gsm);
    uint32_t aoff = (uint32_t)(((r0 + (lane & 15))*KP + (lane >> 4)*8) * 2);
    uint32_t boff = (uint32_t)((((lane >> 4)*8 + (lane & 7))*KP + ((lane >> 3) & 1)*8) * 2);

    float2 pa[8];
    float  pb0[NB], pb1[NB];

    auto load_chunk = [&](int kc) {
        #pragma unroll
        for (int t = 0; t < 8; t++) {
            int i = tid + 256*t;
            int row = i >> 4, c2 = (i & 15) * 2;
            pa[t] = *(const float2*)&A[(size_t)(bm0+row)*K + kc + c2];
        }
        #pragma unroll
        for (int t = 0; t < NB; t++) {
            int i = tid + 256*t;
            int n = i % BN, kk2 = (i / BN) * 2;
            pb0[t] = W[(size_t)(kc+kk2)*NFULL + bn0 + n];
            pb1[t] = W[(size_t)(kc+kk2+1)*NFULL + bn0 + n];
        }
    };
    auto store_chunk = [&](int buf) {
        #pragma unroll
        for (int t = 0; t < 8; t++) {
            int i = tid + 256*t;
            int row = i >> 4, c2 = (i & 15) * 2;
            float2 v = pa[t];
            __nv_bfloat16 h0 = __float2bfloat16(v.x);
            __nv_bfloat16 h1 = __float2bfloat16(v.y);
            __nv_bfloat162 hi; hi.x = h0; hi.y = h1;
            __nv_bfloat162 lo;
            lo.x = __float2bfloat16(v.x - __bfloat162float(h0));
            lo.y = __float2bfloat16(v.y - __bfloat162float(h1));
            int e = buf*2*APL + row*KP + c2;
            *(__nv_bfloat162*)&gsm[e]       = hi;
            *(__nv_bfloat162*)&gsm[e + APL] = lo;
        }
        #pragma unroll
        for (int t = 0; t < NB; t++) {
            int i = tid + 256*t;
            int n = i % BN, kk2 = (i / BN) * 2;
            float x0 = pb0[t], x1 = pb1[t];
            __nv_bfloat16 h0 = __float2bfloat16(x0);
            __nv_bfloat16 h1 = __float2bfloat16(x1);
            __nv_bfloat162 hi; hi.x = h0; hi.y = h1;
            __nv_bfloat162 lo;
            lo.x = __float2bfloat16(x0 - __bfloat162float(h0));
            lo.y = __float2bfloat16(x1 - __bfloat162float(h1));
            int e = BBASE + buf*2*BPL + n*KP + kk2;
            *(__nv_bfloat162*)&gsm[e]       = hi;
            *(__nv_bfloat162*)&gsm[e + BPL] = lo;
        }
    };

    load_chunk(0);
    store_chunk(0);
    __syncthreads();

    int nchunk = K / KC;
    for (int ci = 0; ci < nchunk; ci++) {
        int buf = ci & 1;
        if (ci + 1 < nchunk) load_chunk((ci+1)*KC);

        uint32_t aHi = sm0 + (uint32_t)(buf*2*APL)*2;
        uint32_t aLo = aHi + (uint32_t)APL*2;
        uint32_t bHi = sm0 + (uint32_t)(BBASE + buf*2*BPL)*2;
        uint32_t bLo = bHi + (uint32_t)BPL*2;

        #pragma unroll
        for (int kk = 0; kk < KC; kk += 16) {
            uint32_t ah[4], al[4];
            ldsm4(ah, aHi + aoff + kk*2);
            ldsm4(al, aLo + aoff + kk*2);
            uint32_t bo = boff + kk*2;
            #pragma unroll
            for (int tp = 0; tp < NT8/2; tp++) {
                uint32_t bh[4], bl[4];
                ldsm4(bh, bHi + bo);
                ldsm4(bl, bLo + bo);
                mma_bf16(acc[2*tp],   ah, bh);
                mma_bf16(acc[2*tp],   ah, bl);
                mma_bf16(acc[2*tp],   al, bh);
                mma_bf16(acc[2*tp+1], ah, bh+2);
                mma_bf16(acc[2*tp+1], ah, bl+2);
                mma_bf16(acc[2*tp+1], al, bh+2);
                bo += 16*KP*2;
            }
        }
        if (ci + 1 < nchunk) store_chunk(buf ^ 1);
        __syncthreads();
    }

    int row = bm0 + r0 + (lane >> 2);
    int col = bn0 + (lane & 3)*2;
    #pragma unroll
    for (int t = 0; t < NT8; t++) {
        *(float2*)&C[(size_t)row*NFULL + col + t*8]     = make_float2(acc[t][0], acc[t][1]);
        *(float2*)&C[(size_t)(row+8)*NFULL + col + t*8] = make_float2(acc[t][2], acc[t][3]);
    }
}
#define GEMM1_SMEM ((4*128*40 + 4*128*40) * 2)
#define GEMM2_SMEM ((4*128*40 + 4*64*40) * 2)

// ---------------- fused GAT attention: (x@W0) + alphas + softmax + gather (+pool)
// One CTA per graph, 512 threads (R14-proven structure).
template<int H, int F, bool POOL, bool GEMM0>
__global__ __launch_bounds__(512) void gat_agg_fused(
    const float* __restrict__ Hf, const float* __restrict__ Xin,
    const float* __restrict__ W0,
    const float* __restrict__ asrc, const float* __restrict__ adst,
    const float* __restrict__ bias, float* __restrict__ out)
{
    constexpr int NT = 512;
    constexpr int HF = H*F;
    constexpr int TS = HF + 4;           // row pad
    constexpr int C4 = HF/4;
    constexpr int NPI = NT/C4;
    constexpr int OUT_F = POOL ? 128*F : 0;
    extern __shared__ float sm[];
    float* s_tile = sm;                          // 128*TS
    float* s_als  = s_tile + 128*TS;             // 128*H
    float* s_ald  = s_als + 128*H;               // 128*H
    float* s_inv  = s_ald + 128*H;               // 128*H
    float* s_w    = s_inv + 128*H;               // 128*H*MD2 (also W0/pool scratch)
    float* s_vec  = s_w + 128*H*MD2;             // 3*HF
    float* s_out  = s_vec + 3*HF;                // POOL ? 128*F : 0
    int*   s_adj  = (int*)(s_out + OUT_F);       // 128*MD2
    int*   s_deg  = s_adj + 128*MD2;             // 128

    int tid = threadIdx.x;
    int g0 = blockIdx.x * 128;

    for (int i = tid; i < HF; i += NT) {
        s_vec[i] = asrc[i]; s_vec[HF+i] = adst[i]; s_vec[2*HF+i] = bias[i];
    }
    for (int i = tid; i < 128*MD2; i += NT)
        s_adj[i] = g_adj[(i/MD2)*MD + (i & (MD2-1))];
    if (tid < 128) s_deg[tid] = g_deg[tid];
    if (GEMM0) {
        for (int i = tid; i < NF*HF; i += NT) s_w[i] = W0[i];
    } else {
        for (int i = tid; i < 128*C4; i += NT) {
            int row = i / C4, c = i % C4;
            *(float4*)&s_tile[row*TS + c*4] = *(const float4*)&Hf[(size_t)(g0+row)*HF + c*4];
        }
    }
    __syncthreads();

    if (GEMM0) {
        int n = tid & 127, q = tid >> 7;          // q in 0..3
        float xr[NF];
        #pragma unroll
        for (int k = 0; k < NF; k += 4) {
            float4 v = *(const float4*)&Xin[(size_t)(g0+n)*NF + k];
            xr[k] = v.x; xr[k+1] = v.y; xr[k+2] = v.z; xr[k+3] = v.w;
        }
        for (int c4 = q*(C4/4); c4 < (q+1)*(C4/4); c4++) {
            float4 a = make_float4(0.f, 0.f, 0.f, 0.f);
            #pragma unroll
            for (int k = 0; k < NF; k++) {
                float4 w = *(const float4*)&s_w[k*HF + c4*4];
                a.x += xr[k]*w.x; a.y += xr[k]*w.y; a.z += xr[k]*w.z; a.w += xr[k]*w.w;
            }
            *(float4*)&s_tile[n*TS + c4*4] = a;
        }
        __syncthreads();
    }

    // attention logit dot-products
    {
        int n = tid & 127;
        for (int hh = tid >> 7; hh < H; hh += NT/128) {
            const float* rowp = &s_tile[n*TS + hh*F];
            float ss = 0.f, sd = 0.f;
            #pragma unroll
            for (int c = 0; c < F; c += 4) {
                float4 v = *(const float4*)&rowp[c];
                float4 a = *(const float4*)&s_vec[hh*F + c];
                float4 d = *(const float4*)&s_vec[HF + hh*F + c];
                ss += v.x*a.x + v.y*a.y + v.z*a.z + v.w*a.w;
                sd += v.x*d.x + v.y*d.y + v.z*d.z + v.w*d.w;
            }
            s_als[n*H + hh] = ss; s_ald[n*H + hh] = sd;
        }
    }
    __syncthreads();

    // per-(node, head): single pass exp + sum; 1/den stored
    for (int task = tid; task < 128*H; task += NT) {
        int n = task & 127, hh = task >> 7;
        int dg = s_deg[n];
        float ad = s_ald[n*H + hh];
        float* wp = &s_w[(n*H + hh)*MD2];
        const int* ap = &s_adj[n*MD2];
        float den = 0.f;
        for (int j = 0; j < dg; j++) {
            float e = s_als[ap[j]*H + hh] + ad;
            e = (e > 0.f) ? e : 0.2f*e;           // leaky_relu 0.2
            float a = __expf(e);
            wp[j] = a;
            den += a;
        }
        s_inv[n*H + hh] = 1.f / (den + 1e-16f);
    }
    __syncthreads();

    // gather-accumulate (dual chains)
    for (int it = 0; it < 128/NPI; it++) {
        int n = it*NPI + tid/C4;
        int c4 = tid & (C4-1);
        int hh = (c4*4)/F;
        int dg = s_deg[n];
        const float* wp = &s_w[(n*H + hh)*MD2];
        const int*  ap = &s_adj[n*MD2];
        float4 acc0 = make_float4(0.f, 0.f, 0.f, 0.f);
        float4 acc1 = make_float4(0.f, 0.f, 0.f, 0.f);
        int j = 0;
        for (; j + 2 <= dg; j += 2) {
            float w0 = wp[j], w1 = wp[j+1];
            float4 v0 = *(const float4*)&s_tile[ap[j]*TS + c4*4];
            float4 v1 = *(const float4*)&s_tile[ap[j+1]*TS + c4*4];
            acc0.x += w0*v0.x; acc0.y += w0*v0.y; acc0.z += w0*v0.z; acc0.w += w0*v0.w;
            acc1.x += w1*v1.x; acc1.y += w1*v1.y; acc1.z += w1*v1.z; acc1.w += w1*v1.w;
        }
        if (j < dg) {
            float w0 = wp[j];
            float4 v0 = *(const float4*)&s_tile[ap[j]*TS + c4*4];
            acc0.x += w0*v0.x; acc0.y += w0*v0.y; acc0.z += w0*v0.z; acc0.w += w0*v0.w;
        }
        float inv = s_inv[n*H + hh];
        float4 bb = *(const float4*)&s_vec[2*HF + c4*4];
        float4 o;
        o.x = fmaxf((acc0.x + acc1.x)*inv + bb.x, 0.f);
        o.y = fmaxf((acc0.y + acc1.y)*inv + bb.y, 0.f);
        o.z = fmaxf((acc0.z + acc1.z)*inv + bb.z, 0.f);
        o.w = fmaxf((acc0.w + acc1.w)*inv + bb.w, 0.f);
        if (POOL) *(float4*)&s_out[n*F + c4*4] = o;
        else      *(float4*)&out[(size_t)(g0+n)*HF + c4*4] = o;
    }
    if (POOL) {
        __syncthreads();
        int part = tid >> 6, c = tid & 63;       // 8 parts x 64 channels
        float s = 0.f;
        for (int i = part*16; i < part*16 + 16; i++) s += s_out[i*F + c];
        s_w[part*64 + c] = s;
        __syncthreads();
        if (tid < F) {
            float t = 0.f;
            #pragma unroll
            for (int p = 0; p < 8; p++) t += s_w[p*64 + tid];
            g_embs[blockIdx.x*F + tid] = t;
        }
    }
}
#define AGG01_SMEM ((128*(4*64+4) + 3*128*4 + 128*4*MD2 + 3*256 + 128*MD2 + 128) * 4)
#define AGG2_SMEM  ((128*(64+4)   + 3*128*1 + 128*1*MD2 + 3*64 + 128*64 + 128*MD2 + 128) * 4)

// ---------------- precompute x-part of gates for all timesteps ----------------
__global__ void gx_kernel(const float* __restrict__ Wih_f, const float* __restrict__ bih_f,
                          const float* __restrict__ bhh_f,
                          const float* __restrict__ Wih_b, const float* __restrict__ bih_b,
                          const float* __restrict__ bhh_b)
{
    int bx = blockIdx.x;             // 512 = 2*64*4
    int dir = bx >> 8, t = (bx >> 2) & 63, b = bx & 3;
    __shared__ float xv[HID];
    int tid = threadIdx.x;           // 256
    if (tid < HID) xv[tid] = g_embs[(b*TT + t)*HID + tid];
    __syncthreads();
    const float* Wih = dir ? Wih_b : Wih_f;
    const float* bi  = dir ? bih_b : bih_f;
    const float* bh  = dir ? bhh_b : bhh_f;
    for (int gg = tid; gg < 1024; gg += 256) {
        float acc = bi[gg] + bh[gg];
        #pragma unroll
        for (int k = 0; k < HID; k += 4) {
            float4 w = *(const float4*)&Wih[gg*HID + k];
            acc += w.x*xv[k] + w.y*xv[k+1] + w.z*xv[k+2] + w.w*xv[k+3];
        }
        g_gx[((dir*TT + t)*BSZ + b)*1024 + gg] = acc;
    }
}

// ---------------- cluster-resident BiLSTM, Whh in registers ----------------
// Step sync via mbarrier (TRYWAIT ~90-150 cyc) instead of barrier.cluster
// (~490 cyc): each producer thread stores its h to all 8 peers then does 8
// release-arrives; consumers acquire-wait (256 arrivals/step).
__device__ __forceinline__ float sigm(float x) { return 1.f / (1.f + __expf(-x)); }
__device__ __forceinline__ float tanh_fast(float x) { return 2.f / (1.f + __expf(-2.f*x)) - 1.f; }

__global__ __launch_bounds__(256, 1) __cluster_dims__(8, 1, 1)
void lstm_kernel(const float* __restrict__ Whh_f, const float* __restrict__ Whh_b)
{
    __shared__ float h_s[512];       // double-buffered h (2 x 256)
    __shared__ float part[256];
    __shared__ __align__(8) uint64_t mbar_sto;
    int tid = threadIdx.x;
    uint32_t rank;
    asm("mov.u32 %0, %%cluster_ctarank;" : "=r"(rank));
    int chain = blockIdx.x >> 3;
    int dir = chain >> 2, b = chain & 3;
    const float* W = dir ? Whh_b : Whh_f;
    int r = tid & 127, half = tid >> 7;
    int r_glob = (r >> 5)*256 + 32*(int)rank + (r & 31);
    const float* wp = W + (size_t)r_glob*256 + half*128;
    uint32_t mbar = smem_u32(&mbar_sto);

    float W_r[128];
    #pragma unroll
    for (int i = 0; i < 128; i += 4) {
        float4 v = *(const float4*)&wp[i];
        W_r[i] = v.x; W_r[i+1] = v.y; W_r[i+2] = v.z; W_r[i+3] = v.w;
    }
    if (tid == 0) MBARRIER_INIT(mbar, 256);   // 8 CTAs x 32 producer threads
    h_s[tid] = 0.f;
    float c_val = 0.f;
    __syncthreads();
    // one-time cluster barrier: all mbarriers initialized + h zeroed before
    // any peer stores/arrives can land
    asm volatile("barrier.cluster.arrive.aligned;" ::: "memory");
    asm volatile("barrier.cluster.wait.aligned;" ::: "memory");

    uint32_t h_addr0 = smem_u32(h_s);
    int t0 = dir ? (TT-1) : 0;
    float gxv = (half == 0) ? g_gx[((dir*TT + t0)*BSZ + b)*1024 + r_glob] : 0.f;

    for (int s = 0; s < TT; s++) {
        int p = s & 1;
        const float* hp = &h_s[p*256 + half*128];
        float a0 = 0.f, a1 = 0.f, a2 = 0.f, a3 = 0.f;
        #pragma unroll
        for (int k = 0; k < 128; k += 16) {
            float4 h0 = *(const float4*)&hp[k];
            float4 h1 = *(const float4*)&hp[k+4];
            float4 h2 = *(const float4*)&hp[k+8];
            float4 h3 = *(const float4*)&hp[k+12];
            a0 += W_r[k+0]*h0.x  + W_r[k+1]*h0.y  + W_r[k+2]*h0.z  + W_r[k+3]*h0.w;
            a1 += W_r[k+4]*h1.x  + W_r[k+5]*h1.y  + W_r[k+6]*h1.z  + W_r[k+7]*h1.w;
            a2 += W_r[k+8]*h2.x  + W_r[k+9]*h2.y  + W_r[k+10]*h2.z + W_r[k+11]*h2.w;
            a3 += W_r[k+12]*h3.x + W_r[k+13]*h3.y + W_r[k+14]*h3.z + W_r[k+15]*h3.w;
        }
        float acc = gxv + ((a0 + a1) + (a2 + a3));
        if (s+1 < TT && half == 0) {
            int tn = dir ? (TT-2-s) : (s+1);
            gxv = g_gx[((dir*TT + tn)*BSZ + b)*1024 + r_glob];
        }
        part[tid] = acc;
        __syncthreads();    // orders all local h_s[p] reads before producer arrives
        if (tid < 32) {
            float ig = sigm (part[tid]      + part[tid+128]);
            float fg = sigm (part[tid+32]   + part[tid+160]);
            float gg = tanh_fast(part[tid+64] + part[tid+192]);
            float og = sigm (part[tid+96]   + part[tid+224]);
            c_val = fg*c_val + ig*gg;
            float hv = og*tanh_fast(c_val);
            uint32_t laddr = h_addr0 + ((uint32_t)((p^1)*256 + 32*rank + tid) << 2);
            #pragma unroll
            for (int pe = 0; pe < 8; pe++) st_cluster_f32(laddr, (uint32_t)pe, hv);
            if (s == TT-1)
                g_hT[(dir*BSZ + b)*RH + 32*(int)rank + tid] = hv;
            #pragma unroll
            for (int pe = 0; pe < 8; pe++) MBAR_ARRIVE_REL_CLUSTER(mbar, (uint32_t)pe);
        }
        MBAR_WAIT_CLUSTER(mbar, s & 1);
    }
}

// ---------------- heads + Poincare projection ----------------
__global__ void head_kernel(const float* __restrict__ muW, const float* __restrict__ mub,
                            const float* __restrict__ lvW, const float* __restrict__ lvb,
                            float* __restrict__ out)
{
    int b = blockIdx.x;     // 4
    int l = threadIdx.x;    // 64
    __shared__ float feat[2*RH];
    __shared__ float red[LD];
    for (int i = l; i < 2*RH; i += LD)
        feat[i] = (i < RH) ? g_hT[b*RH + i] : g_hT[(BSZ + b)*RH + (i - RH)];
    __syncthreads();
    float mu = mub[l], lv = lvb[l];
    #pragma unroll 4
    for (int k = 0; k < 2*RH; k++) {
        float f = feat[k];
        mu += muW[l*2*RH + k]*f;
        lv += lvW[l*2*RH + k]*f;
    }
    red[l] = mu*mu;
    __syncthreads();
    if (l == 0) {
        float s = 0.f;
        for (int i = 0; i < LD; i++) s += red[i];
        red[0] = sqrtf(s);
    }
    __syncthreads();
    float nrm = red[0];
    const float maxnorm = 1.0f - 4e-3f;
    float scale = (nrm > maxnorm) ? (maxnorm / nrm) : 1.f;
    out[b*LD + l] = mu*scale;            // mu  [4,64]
    out[BSZ*LD + b*LD + l] = lv;         // logvar [4,64]
}

// ---------------- launch ----------------
extern "C" void kernel_launch(void* const* d_in, const int* in_sizes, int n_in,
                              void* d_out, int out_size)
{
    const float* x      = (const float*)d_in[0];
    const int*   ei     = (const int*)  d_in[1];
    const float* g0W    = (const float*)d_in[2];
    const float* g0as   = (const float*)d_in[3];
    const float* g0ad   = (const float*)d_in[4];
    const float* g0b    = (const float*)d_in[5];
    const float* g1W    = (const float*)d_in[6];
    const float* g1as   = (const float*)d_in[7];
    const float* g1ad   = (const float*)d_in[8];
    const float* g1b    = (const float*)d_in[9];
    const float* g2W    = (const float*)d_in[10];
    const float* g2as   = (const float*)d_in[11];
    const float* g2ad   = (const float*)d_in[12];
    const float* g2b    = (const float*)d_in[13];
    const float* Wih_f  = (const float*)d_in[14];
    const float* Whh_f  = (const float*)d_in[15];
    const float* bih_f  = (const float*)d_in[16];
    const float* bhh_f  = (const float*)d_in[17];
    const float* Wih_b  = (const float*)d_in[18];
    const float* Whh_b  = (const float*)d_in[19];
    const float* bih_b  = (const float*)d_in[20];
    const float* bhh_b  = (const float*)d_in[21];
    const float* muW    = (const float*)d_in[22];
    const float* mub    = (const float*)d_in[23];
    const float* lvW    = (const float*)d_in[24];
    const float* lvb    = (const float*)d_in[25];
    float* out = (float*)d_out;

    float *bufA, *bufB;
    cudaGetSymbolAddress((void**)&bufA, g_bufA);
    cudaGetSymbolAddress((void**)&bufB, g_bufB);

    cudaFuncSetAttribute(gat_agg_fused<4,64,false,true>,
                         cudaFuncAttributeMaxDynamicSharedMemorySize, AGG01_SMEM);
    cudaFuncSetAttribute(gat_agg_fused<4,64,false,false>,
                         cudaFuncAttributeMaxDynamicSharedMemorySize, AGG01_SMEM);
    cudaFuncSetAttribute(gat_agg_fused<1,64,true,false>,
                         cudaFuncAttributeMaxDynamicSharedMemorySize, AGG2_SMEM);
    cudaFuncSetAttribute(hmma_gemm<256,128>,
                         cudaFuncAttributeMaxDynamicSharedMemorySize, GEMM1_SMEM);
    cudaFuncSetAttribute(hmma_gemm<64,64>,
                         cudaFuncAttributeMaxDynamicSharedMemorySize, GEMM2_SMEM);

    // 1) adjacency (deterministic, parallel)
    build_adj_kernel<<<1, 1024>>>(ei);

    // 2) GAT layer 0: fused (x@W0) + attention
    gat_agg_fused<4,64,false,true><<<NG, 512, AGG01_SMEM>>>(
        nullptr, x, g0W, g0as, g0ad, g0b, bufA);

    // 3) GAT layer 1: HMMA bf16x3 (pipelined) + fused attention
    hmma_gemm<256,128><<<dim3(NTOT/128, 2), 256, GEMM1_SMEM>>>(bufA, g1W, bufB, 256);
    gat_agg_fused<4,64,false,false><<<NG, 512, AGG01_SMEM>>>(
        bufB, nullptr, nullptr, g1as, g1ad, g1b, bufA);

    // 4) GAT layer 2: HMMA (pipelined) + fused attention + pool
    hmma_gemm<64,64><<<dim3(NTOT/128, 1), 256, GEMM2_SMEM>>>(bufA, g2W, bufB, 256);
    gat_agg_fused<1,64,true,false><<<NG, 512, AGG2_SMEM>>>(
        bufB, nullptr, nullptr, g2as, g2ad, g2b, bufA);

    // 5) precompute x-part of gates
    gx_kernel<<<2*TT*BSZ, 256>>>(Wih_f, bih_f, bhh_f, Wih_b, bih_b, bhh_b);

    // 6) cluster-resident BiLSTM: 8 chains x 8-CTA clusters, mbarrier-synced
    lstm_kernel<<<64, 256>>>(Whh_f, Whh_b);

    // 7) heads + Poincare projection
    head_kernel<<<BSZ, LD>>>(muW, mub, lvW, lvb, out);
}

// round 17
// speedup vs baseline: 1.2880x; 1.2880x over previous
#include <cuda_runtime.h>
#include <cuda_bf16.h>
#include <math.h>
#include <stdint.h>

// ---------------- problem constants ----------------
#define BSZ   4
#define TT    64
#define NNODE 128
#define NF    16
#define HID   64
#define HEADS 4
#define RH    256
#define LD    64
#define EPG   1024
#define NG    (BSZ*TT)        // 256 graphs
#define NTOT  (NG*NNODE)      // 32768 nodes
#define MD    64              // adjacency capacity in g_adj
#define MD2   32              // capacity used by fused agg (actual deg ~9-20)

// ---------------- device scratch ----------------
__device__ float g_bufA[NTOT*256];           // 32 MB
__device__ float g_bufB[NTOT*256];           // 32 MB
__device__ int   g_adj[NNODE*MD];
__device__ int   g_deg[NNODE];
__device__ float g_embs[NG*HID];             // graph embeddings
__device__ float g_gx[2*TT*BSZ*1024];        // precomputed x@Wih^T + biases
__device__ float g_hT[2*BSZ*RH];             // final hidden states

// ---------------- small PTX helpers ----------------
__device__ __forceinline__ uint32_t smem_u32(const void* p) {
    uint32_t a;
    asm("{ .reg .u64 t; cvta.to.shared.u64 t, %1; cvt.u32.u64 %0, t; }" : "=r"(a) : "l"(p));
    return a;
}
__device__ __forceinline__ void st_cluster_f32(uint32_t laddr, uint32_t rank, float v) {
    uint32_t ra;
    asm volatile("mapa.shared::cluster.u32 %0, %1, %2;" : "=r"(ra) : "r"(laddr), "r"(rank));
    asm volatile("st.shared::cluster.f32 [%0], %1;" :: "r"(ra), "f"(v) : "memory");
}
__device__ __forceinline__ void mma_bf16(float* c, const uint32_t* a, const uint32_t* b) {
    asm volatile(
        "mma.sync.aligned.m16n8k16.row.col.f32.bf16.bf16.f32 "
        "{%0,%1,%2,%3}, {%4,%5,%6,%7}, {%8,%9}, {%0,%1,%2,%3};"
        : "+f"(c[0]), "+f"(c[1]), "+f"(c[2]), "+f"(c[3])
        : "r"(a[0]), "r"(a[1]), "r"(a[2]), "r"(a[3]), "r"(b[0]), "r"(b[1]));
}
__device__ __forceinline__ void ldsm4(uint32_t* r, uint32_t addr) {
    asm volatile("ldmatrix.sync.aligned.m8n8.x4.shared.b16 {%0,%1,%2,%3}, [%4];"
        : "=r"(r[0]), "=r"(r[1]), "=r"(r[2]), "=r"(r[3]) : "r"(addr));
}

// ---------------- CSR build (deterministic, parallel prefix) ----------------
__global__ __launch_bounds__(1024) void build_adj_kernel(const int* __restrict__ ei) {
    __shared__ int ss[EPG];
    __shared__ int sd[EPG];
    __shared__ int cnts[8][NNODE];
    int tid = threadIdx.x;
    for (int e = tid; e < EPG; e += 1024) { ss[e] = ei[e]; sd[e] = ei[EPG + e]; }
    __syncthreads();
    int d = tid & 127, seg = tid >> 7;       // 8 segments x 128 dst
    int e0 = seg * 128;
    int cnt = 0;
    for (int e = e0; e < e0 + 128; e++) cnt += (sd[e] == d);
    cnts[seg][d] = cnt;
    __syncthreads();
    int o = 0;
    for (int s2 = 0; s2 < seg; s2++) o += cnts[s2][d];
    for (int e = e0; e < e0 + 128; e++) {
        if (sd[e] == d && o < MD-1) g_adj[d*MD + o++] = ss[e];
    }
    if (seg == 7) {                          // last segment appends self loop
        g_adj[d*MD + o] = d;
        g_deg[d] = o + 1;
    }
}

// ---------------- HMMA bf16x3 GEMM, double-buffered pipeline ---------------
template<int NFULL, int BN>
__global__ __launch_bounds__(256) void hmma_gemm(
    const float* __restrict__ A, const float* __restrict__ W,
    float* __restrict__ C, int K)
{
    constexpr int KC = 32;
    constexpr int KP = 40;
    constexpr int NT8 = BN/8;
    constexpr int NB  = BN/16;               // B float-pairs per thread
    extern __shared__ __align__(16) __nv_bfloat16 gsm[];
    constexpr int APL = 128*KP;              // A plane elems
    constexpr int BPL = BN*KP;               // B plane elems
    constexpr int BBASE = 4*APL;

    int tid = threadIdx.x;
    int wid = tid >> 5, lane = tid & 31;
    int bm0 = blockIdx.x * 128;
    int bn0 = blockIdx.y * BN;
    int r0 = wid * 16;

    float acc[NT8][4];
    #pragma unroll
    for (int t = 0; t < NT8; t++)
        #pragma unroll
        for (int i = 0; i < 4; i++) acc[t][i] = 0.f;

    uint32_t sm0 = smem_u32(gsm);
    uint32_t aoff = (uint32_t)(((r0 + (lane & 15))*KP + (lane >> 4)*8) * 2);
    uint32_t boff = (uint32_t)((((lane >> 4)*8 + (lane & 7))*KP + ((lane >> 3) & 1)*8) * 2);

    float2 pa[8];
    float  pb0[NB], pb1[NB];

    auto load_chunk = [&](int kc) {
        #pragma unroll
        for (int t = 0; t < 8; t++) {
            int i = tid + 256*t;
            int row = i >> 4, c2 = (i & 15) * 2;
            pa[t] = *(const float2*)&A[(size_t)(bm0+row)*K + kc + c2];
        }
        #pragma unroll
        for (int t = 0; t < NB; t++) {
            int i = tid + 256*t;
            int n = i % BN, kk2 = (i / BN) * 2;
            pb0[t] = W[(size_t)(kc+kk2)*NFULL + bn0 + n];
            pb1[t] = W[(size_t)(kc+kk2+1)*NFULL + bn0 + n];
        }
    };
    auto store_chunk = [&](int buf) {
        #pragma unroll
        for (int t = 0; t < 8; t++) {
            int i = tid + 256*t;
            int row = i >> 4, c2 = (i & 15) * 2;
            float2 v = pa[t];
            __nv_bfloat16 h0 = __float2bfloat16(v.x);
            __nv_bfloat16 h1 = __float2bfloat16(v.y);
            __nv_bfloat162 hi; hi.x = h0; hi.y = h1;
            __nv_bfloat162 lo;
            lo.x = __float2bfloat16(v.x - __bfloat162float(h0));
            lo.y = __float2bfloat16(v.y - __bfloat162float(h1));
            int e = buf*2*APL + row*KP + c2;
            *(__nv_bfloat162*)&gsm[e]       = hi;
            *(__nv_bfloat162*)&gsm[e + APL] = lo;
        }
        #pragma unroll
        for (int t = 0; t < NB; t++) {
            int i = tid + 256*t;
            int n = i % BN, kk2 = (i / BN) * 2;
            float x0 = pb0[t], x1 = pb1[t];
            __nv_bfloat16 h0 = __float2bfloat16(x0);
            __nv_bfloat16 h1 = __float2bfloat16(x1);
            __nv_bfloat162 hi; hi.x = h0; hi.y = h1;
            __nv_bfloat162 lo;
            lo.x = __float2bfloat16(x0 - __bfloat162float(h0));
            lo.y = __float2bfloat16(x1 - __bfloat162float(h1));
            int e = BBASE + buf*2*BPL + n*KP + kk2;
            *(__nv_bfloat162*)&gsm[e]       = hi;
            *(__nv_bfloat162*)&gsm[e + BPL] = lo;
        }
    };

    load_chunk(0);
    store_chunk(0);
    __syncthreads();

    int nchunk = K / KC;
    for (int ci = 0; ci < nchunk; ci++) {
        int buf = ci & 1;
        if (ci + 1 < nchunk) load_chunk((ci+1)*KC);

        uint32_t aHi = sm0 + (uint32_t)(buf*2*APL)*2;
        uint32_t aLo = aHi + (uint32_t)APL*2;
        uint32_t bHi = sm0 + (uint32_t)(BBASE + buf*2*BPL)*2;
        uint32_t bLo = bHi + (uint32_t)BPL*2;

        #pragma unroll
        for (int kk = 0; kk < KC; kk += 16) {
            uint32_t ah[4], al[4];
            ldsm4(ah, aHi + aoff + kk*2);
            ldsm4(al, aLo + aoff + kk*2);
            uint32_t bo = boff + kk*2;
            #pragma unroll
            for (int tp = 0; tp < NT8/2; tp++) {
                uint32_t bh[4], bl[4];
                ldsm4(bh, bHi + bo);
                ldsm4(bl, bLo + bo);
                mma_bf16(acc[2*tp],   ah, bh);
                mma_bf16(acc[2*tp],   ah, bl);
                mma_bf16(acc[2*tp],   al, bh);
                mma_bf16(acc[2*tp+1], ah, bh+2);
                mma_bf16(acc[2*tp+1], ah, bl+2);
                mma_bf16(acc[2*tp+1], al, bh+2);
                bo += 16*KP*2;
            }
        }
        if (ci + 1 < nchunk) store_chunk(buf ^ 1);
        __syncthreads();
    }

    int row = bm0 + r0 + (lane >> 2);
    int col = bn0 + (lane & 3)*2;
    #pragma unroll
    for (int t = 0; t < NT8; t++) {
        *(float2*)&C[(size_t)row*NFULL + col + t*8]     = make_float2(acc[t][0], acc[t][1]);
        *(float2*)&C[(size_t)(row+8)*NFULL + col + t*8] = make_float2(acc[t][2], acc[t][3]);
    }
}
#define GEMM1_SMEM ((4*128*40 + 4*128*40) * 2)
#define GEMM2_SMEM ((4*128*40 + 4*64*40) * 2)

// ---------------- fused GAT attention: (x@W0) + alphas + softmax + gather (+pool)
// One CTA per graph, 512 threads (R14-proven structure).
template<int H, int F, bool POOL, bool GEMM0>
__global__ __launch_bounds__(512) void gat_agg_fused(
    const float* __restrict__ Hf, const float* __restrict__ Xin,
    const float* __restrict__ W0,
    const float* __restrict__ asrc, const float* __restrict__ adst,
    const float* __restrict__ bias, float* __restrict__ out)
{
    constexpr int NT = 512;
    constexpr int HF = H*F;
    constexpr int TS = HF + 4;           // row pad
    constexpr int C4 = HF/4;
    constexpr int NPI = NT/C4;
    constexpr int OUT_F = POOL ? 128*F : 0;
    extern __shared__ float sm[];
    float* s_tile = sm;                          // 128*TS
    float* s_als  = s_tile + 128*TS;             // 128*H
    float* s_ald  = s_als + 128*H;               // 128*H
    float* s_inv  = s_ald + 128*H;               // 128*H
    float* s_w    = s_inv + 128*H;               // 128*H*MD2 (also W0/pool scratch)
    float* s_vec  = s_w + 128*H*MD2;             // 3*HF
    float* s_out  = s_vec + 3*HF;                // POOL ? 128*F : 0
    int*   s_adj  = (int*)(s_out + OUT_F);       // 128*MD2
    int*   s_deg  = s_adj + 128*MD2;             // 128

    int tid = threadIdx.x;
    int g0 = blockIdx.x * 128;

    for (int i = tid; i < HF; i += NT) {
        s_vec[i] = asrc[i]; s_vec[HF+i] = adst[i]; s_vec[2*HF+i] = bias[i];
    }
    for (int i = tid; i < 128*MD2; i += NT)
        s_adj[i] = g_adj[(i/MD2)*MD + (i & (MD2-1))];
    if (tid < 128) s_deg[tid] = g_deg[tid];
    if (GEMM0) {
        for (int i = tid; i < NF*HF; i += NT) s_w[i] = W0[i];
    } else {
        for (int i = tid; i < 128*C4; i += NT) {
            int row = i / C4, c = i % C4;
            *(float4*)&s_tile[row*TS + c*4] = *(const float4*)&Hf[(size_t)(g0+row)*HF + c*4];
        }
    }
    __syncthreads();

    if (GEMM0) {
        int n = tid & 127, q = tid >> 7;          // q in 0..3
        float xr[NF];
        #pragma unroll
        for (int k = 0; k < NF; k += 4) {
            float4 v = *(const float4*)&Xin[(size_t)(g0+n)*NF + k];
            xr[k] = v.x; xr[k+1] = v.y; xr[k+2] = v.z; xr[k+3] = v.w;
        }
        for (int c4 = q*(C4/4); c4 < (q+1)*(C4/4); c4++) {
            float4 a = make_float4(0.f, 0.f, 0.f, 0.f);
            #pragma unroll
            for (int k = 0; k < NF; k++) {
                float4 w = *(const float4*)&s_w[k*HF + c4*4];
                a.x += xr[k]*w.x; a.y += xr[k]*w.y; a.z += xr[k]*w.z; a.w += xr[k]*w.w;
            }
            *(float4*)&s_tile[n*TS + c4*4] = a;
        }
        __syncthreads();
    }

    // attention logit dot-products
    {
        int n = tid & 127;
        for (int hh = tid >> 7; hh < H; hh += NT/128) {
            const float* rowp = &s_tile[n*TS + hh*F];
            float ss = 0.f, sd = 0.f;
            #pragma unroll
            for (int c = 0; c < F; c += 4) {
                float4 v = *(const float4*)&rowp[c];
                float4 a = *(const float4*)&s_vec[hh*F + c];
                float4 d = *(const float4*)&s_vec[HF + hh*F + c];
                ss += v.x*a.x + v.y*a.y + v.z*a.z + v.w*a.w;
                sd += v.x*d.x + v.y*d.y + v.z*d.z + v.w*d.w;
            }
            s_als[n*H + hh] = ss; s_ald[n*H + hh] = sd;
        }
    }
    __syncthreads();

    // per-(node, head): single pass exp + sum; 1/den stored
    for (int task = tid; task < 128*H; task += NT) {
        int n = task & 127, hh = task >> 7;
        int dg = s_deg[n];
        float ad = s_ald[n*H + hh];
        float* wp = &s_w[(n*H + hh)*MD2];
        const int* ap = &s_adj[n*MD2];
        float den = 0.f;
        for (int j = 0; j < dg; j++) {
            float e = s_als[ap[j]*H + hh] + ad;
            e = (e > 0.f) ? e : 0.2f*e;           // leaky_relu 0.2
            float a = __expf(e);
            wp[j] = a;
            den += a;
        }
        s_inv[n*H + hh] = 1.f / (den + 1e-16f);
    }
    __syncthreads();

    // gather-accumulate (dual chains)
    for (int it = 0; it < 128/NPI; it++) {
        int n = it*NPI + tid/C4;
        int c4 = tid & (C4-1);
        int hh = (c4*4)/F;
        int dg = s_deg[n];
        const float* wp = &s_w[(n*H + hh)*MD2];
        const int*  ap = &s_adj[n*MD2];
        float4 acc0 = make_float4(0.f, 0.f, 0.f, 0.f);
        float4 acc1 = make_float4(0.f, 0.f, 0.f, 0.f);
        int j = 0;
        for (; j + 2 <= dg; j += 2) {
            float w0 = wp[j], w1 = wp[j+1];
            float4 v0 = *(const float4*)&s_tile[ap[j]*TS + c4*4];
            float4 v1 = *(const float4*)&s_tile[ap[j+1]*TS + c4*4];
            acc0.x += w0*v0.x; acc0.y += w0*v0.y; acc0.z += w0*v0.z; acc0.w += w0*v0.w;
            acc1.x += w1*v1.x; acc1.y += w1*v1.y; acc1.z += w1*v1.z; acc1.w += w1*v1.w;
        }
        if (j < dg) {
            float w0 = wp[j];
            float4 v0 = *(const float4*)&s_tile[ap[j]*TS + c4*4];
            acc0.x += w0*v0.x; acc0.y += w0*v0.y; acc0.z += w0*v0.z; acc0.w += w0*v0.w;
        }
        float inv = s_inv[n*H + hh];
        float4 bb = *(const float4*)&s_vec[2*HF + c4*4];
        float4 o;
        o.x = fmaxf((acc0.x + acc1.x)*inv + bb.x, 0.f);
        o.y = fmaxf((acc0.y + acc1.y)*inv + bb.y, 0.f);
        o.z = fmaxf((acc0.z + acc1.z)*inv + bb.z, 0.f);
        o.w = fmaxf((acc0.w + acc1.w)*inv + bb.w, 0.f);
        if (POOL) *(float4*)&s_out[n*F + c4*4] = o;
        else      *(float4*)&out[(size_t)(g0+n)*HF + c4*4] = o;
    }
    if (POOL) {
        __syncthreads();
        int part = tid >> 6, c = tid & 63;       // 8 parts x 64 channels
        float s = 0.f;
        for (int i = part*16; i < part*16 + 16; i++) s += s_out[i*F + c];
        s_w[part*64 + c] = s;
        __syncthreads();
        if (tid < F) {
            float t = 0.f;
            #pragma unroll
            for (int p = 0; p < 8; p++) t += s_w[p*64 + tid];
            g_embs[blockIdx.x*F + tid] = t;
        }
    }
}
#define AGG01_SMEM ((128*(4*64+4) + 3*128*4 + 128*4*MD2 + 3*256 + 128*MD2 + 128) * 4)
#define AGG2_SMEM  ((128*(64+4)   + 3*128*1 + 128*1*MD2 + 3*64 + 128*64 + 128*MD2 + 128) * 4)

// ---------------- precompute x-part of gates, batch-amortized ----------------
// grid = 2*TT blocks: block = (dir, t) computes all BSZ batches, so each Wih
// row is read once per block and reused 4x (L2 traffic 131MB -> 33MB).
// Inner-k summation order identical to the reference formulation.
__global__ __launch_bounds__(256) void gx_kernel(
    const float* __restrict__ Wih_f, const float* __restrict__ bih_f,
    const float* __restrict__ bhh_f,
    const float* __restrict__ Wih_b, const float* __restrict__ bih_b,
    const float* __restrict__ bhh_b)
{
    int bx = blockIdx.x;             // 128 = 2*64
    int dir = bx >> 6, t = bx & 63;
    __shared__ float xv[BSZ][HID];
    int tid = threadIdx.x;           // 256
    if (tid < BSZ*HID) xv[tid >> 6][tid & 63] = g_embs[((tid >> 6)*TT + t)*HID + (tid & 63)];
    __syncthreads();
    const float* Wih = dir ? Wih_b : Wih_f;
    const float* bi  = dir ? bih_b : bih_f;
    const float* bh  = dir ? bhh_b : bhh_f;
    for (int gg = tid; gg < 1024; gg += 256) {
        float base = bi[gg] + bh[gg];
        float acc0 = base, acc1 = base, acc2 = base, acc3 = base;
        #pragma unroll
        for (int k = 0; k < HID; k += 4) {
            float4 w = *(const float4*)&Wih[gg*HID + k];
            acc0 += w.x*xv[0][k] + w.y*xv[0][k+1] + w.z*xv[0][k+2] + w.w*xv[0][k+3];
            acc1 += w.x*xv[1][k] + w.y*xv[1][k+1] + w.z*xv[1][k+2] + w.w*xv[1][k+3];
            acc2 += w.x*xv[2][k] + w.y*xv[2][k+1] + w.z*xv[2][k+2] + w.w*xv[2][k+3];
            acc3 += w.x*xv[3][k] + w.y*xv[3][k+1] + w.z*xv[3][k+2] + w.w*xv[3][k+3];
        }
        g_gx[((dir*TT + t)*BSZ + 0)*1024 + gg] = acc0;
        g_gx[((dir*TT + t)*BSZ + 1)*1024 + gg] = acc1;
        g_gx[((dir*TT + t)*BSZ + 2)*1024 + gg] = acc2;
        g_gx[((dir*TT + t)*BSZ + 3)*1024 + gg] = acc3;
    }
}

// ---------------- cluster-resident BiLSTM, Whh in registers ----------------
__device__ __forceinline__ float sigm(float x) { return 1.f / (1.f + __expf(-x)); }
__device__ __forceinline__ float tanh_fast(float x) { return 2.f / (1.f + __expf(-2.f*x)) - 1.f; }

__global__ __launch_bounds__(256, 1) __cluster_dims__(8, 1, 1)
void lstm_kernel(const float* __restrict__ Whh_f, const float* __restrict__ Whh_b)
{
    __shared__ float h_s[512];       // double-buffered h (2 x 256)
    __shared__ float part[256];
    int tid = threadIdx.x;
    uint32_t rank;
    asm("mov.u32 %0, %%cluster_ctarank;" : "=r"(rank));
    int chain = blockIdx.x >> 3;
    int dir = chain >> 2, b = chain & 3;
    const float* W = dir ? Whh_b : Whh_f;
    int r = tid & 127, half = tid >> 7;
    int r_glob = (r >> 5)*256 + 32*(int)rank + (r & 31);
    const float* wp = W + (size_t)r_glob*256 + half*128;

    float W_r[128];
    #pragma unroll
    for (int i = 0; i < 128; i += 4) {
        float4 v = *(const float4*)&wp[i];
        W_r[i] = v.x; W_r[i+1] = v.y; W_r[i+2] = v.z; W_r[i+3] = v.w;
    }
    h_s[tid] = 0.f;
    float c_val = 0.f;
    __syncthreads();
    asm volatile("barrier.cluster.arrive.aligned;" ::: "memory");
    asm volatile("barrier.cluster.wait.aligned;" ::: "memory");

    uint32_t h_addr0 = smem_u32(h_s);
    int t0 = dir ? (TT-1) : 0;
    float gxv = (half == 0) ? g_gx[((dir*TT + t0)*BSZ + b)*1024 + r_glob] : 0.f;

    for (int s = 0; s < TT; s++) {
        int p = s & 1;
        const float* hp = &h_s[p*256 + half*128];
        float a0 = 0.f, a1 = 0.f, a2 = 0.f, a3 = 0.f;
        #pragma unroll
        for (int k = 0; k < 128; k += 16) {
            float4 h0 = *(const float4*)&hp[k];
            float4 h1 = *(const float4*)&hp[k+4];
            float4 h2 = *(const float4*)&hp[k+8];
            float4 h3 = *(const float4*)&hp[k+12];
            a0 += W_r[k+0]*h0.x  + W_r[k+1]*h0.y  + W_r[k+2]*h0.z  + W_r[k+3]*h0.w;
            a1 += W_r[k+4]*h1.x  + W_r[k+5]*h1.y  + W_r[k+6]*h1.z  + W_r[k+7]*h1.w;
            a2 += W_r[k+8]*h2.x  + W_r[k+9]*h2.y  + W_r[k+10]*h2.z + W_r[k+11]*h2.w;
            a3 += W_r[k+12]*h3.x + W_r[k+13]*h3.y + W_r[k+14]*h3.z + W_r[k+15]*h3.w;
        }
        float acc = gxv + ((a0 + a1) + (a2 + a3));
        if (s+1 < TT && half == 0) {
            int tn = dir ? (TT-2-s) : (s+1);
            gxv = g_gx[((dir*TT + tn)*BSZ + b)*1024 + r_glob];
        }
        part[tid] = acc;
        __syncthreads();
        if (tid < 32) {
            float ig = sigm (part[tid]      + part[tid+128]);
            float fg = sigm (part[tid+32]   + part[tid+160]);
            float gg = tanh_fast(part[tid+64] + part[tid+192]);
            float og = sigm (part[tid+96]   + part[tid+224]);
            c_val = fg*c_val + ig*gg;
            float hv = og*tanh_fast(c_val);
            uint32_t laddr = h_addr0 + ((uint32_t)((p^1)*256 + 32*rank + tid) << 2);
            #pragma unroll
            for (int pe = 0; pe < 8; pe++) st_cluster_f32(laddr, (uint32_t)pe, hv);
            if (s == TT-1)
                g_hT[(dir*BSZ + b)*RH + 32*(int)rank + tid] = hv;
        }
        asm volatile("barrier.cluster.arrive.aligned;" ::: "memory");
        asm volatile("barrier.cluster.wait.aligned;" ::: "memory");
    }
}

// ---------------- heads + Poincare projection ----------------
__global__ void head_kernel(const float* __restrict__ muW, const float* __restrict__ mub,
                            const float* __restrict__ lvW, const float* __restrict__ lvb,
                            float* __restrict__ out)
{
    int b = blockIdx.x;     // 4
    int l = threadIdx.x;    // 64
    __shared__ float feat[2*RH];
    __shared__ float red[LD];
    for (int i = l; i < 2*RH; i += LD)
        feat[i] = (i < RH) ? g_hT[b*RH + i] : g_hT[(BSZ + b)*RH + (i - RH)];
    __syncthreads();
    float mu = mub[l], lv = lvb[l];
    #pragma unroll 4
    for (int k = 0; k < 2*RH; k++) {
        float f = feat[k];
        mu += muW[l*2*RH + k]*f;
        lv += lvW[l*2*RH + k]*f;
    }
    red[l] = mu*mu;
    __syncthreads();
    if (l == 0) {
        float s = 0.f;
        for (int i = 0; i < LD; i++) s += red[i];
        red[0] = sqrtf(s);
    }
    __syncthreads();
    float nrm = red[0];
    const float maxnorm = 1.0f - 4e-3f;
    float scale = (nrm > maxnorm) ? (maxnorm / nrm) : 1.f;
    out[b*LD + l] = mu*scale;            // mu  [4,64]
    out[BSZ*LD + b*LD + l] = lv;         // logvar [4,64]
}

// ---------------- launch ----------------
extern "C" void kernel_launch(void* const* d_in, const int* in_sizes, int n_in,
                              void* d_out, int out_size)
{
    const float* x      = (const float*)d_in[0];
    const int*   ei     = (const int*)  d_in[1];
    const float* g0W    = (const float*)d_in[2];
    const float* g0as   = (const float*)d_in[3];
    const float* g0ad   = (const float*)d_in[4];
    const float* g0b    = (const float*)d_in[5];
    const float* g1W    = (const float*)d_in[6];
    const float* g1as   = (const float*)d_in[7];
    const float* g1ad   = (const float*)d_in[8];
    const float* g1b    = (const float*)d_in[9];
    const float* g2W    = (const float*)d_in[10];
    const float* g2as   = (const float*)d_in[11];
    const float* g2ad   = (const float*)d_in[12];
    const float* g2b    = (const float*)d_in[13];
    const float* Wih_f  = (const float*)d_in[14];
    const float* Whh_f  = (const float*)d_in[15];
    const float* bih_f  = (const float*)d_in[16];
    const float* bhh_f  = (const float*)d_in[17];
    const float* Wih_b  = (const float*)d_in[18];
    const float* Whh_b  = (const float*)d_in[19];
    const float* bih_b  = (const float*)d_in[20];
    const float* bhh_b  = (const float*)d_in[21];
    const float* muW    = (const float*)d_in[22];
    const float* mub    = (const float*)d_in[23];
    const float* lvW    = (const float*)d_in[24];
    const float* lvb    = (const float*)d_in[25];
    float* out = (float*)d_out;

    float *bufA, *bufB;
    cudaGetSymbolAddress((void**)&bufA, g_bufA);
    cudaGetSymbolAddress((void**)&bufB, g_bufB);

    cudaFuncSetAttribute(gat_agg_fused<4,64,false,true>,
                         cudaFuncAttributeMaxDynamicSharedMemorySize, AGG01_SMEM);
    cudaFuncSetAttribute(gat_agg_fused<4,64,false,false>,
                         cudaFuncAttributeMaxDynamicSharedMemorySize, AGG01_SMEM);
    cudaFuncSetAttribute(gat_agg_fused<1,64,true,false>,
                         cudaFuncAttributeMaxDynamicSharedMemorySize, AGG2_SMEM);
    cudaFuncSetAttribute(hmma_gemm<256,128>,
                         cudaFuncAttributeMaxDynamicSharedMemorySize, GEMM1_SMEM);
    cudaFuncSetAttribute(hmma_gemm<64,64>,
                         cudaFuncAttributeMaxDynamicSharedMemorySize, GEMM2_SMEM);

    // 1) adjacency (deterministic, parallel)
    build_adj_kernel<<<1, 1024>>>(ei);

    // 2) GAT layer 0: fused (x@W0) + attention
    gat_agg_fused<4,64,false,true><<<NG, 512, AGG01_SMEM>>>(
        nullptr, x, g0W, g0as, g0ad, g0b, bufA);

    // 3) GAT layer 1: HMMA bf16x3 (pipelined) + fused attention
    hmma_gemm<256,128><<<dim3(NTOT/128, 2), 256, GEMM1_SMEM>>>(bufA, g1W, bufB, 256);
    gat_agg_fused<4,64,false,false><<<NG, 512, AGG01_SMEM>>>(
        bufB, nullptr, nullptr, g1as, g1ad, g1b, bufA);

    // 4) GAT layer 2: HMMA (pipelined) + fused attention + pool
    hmma_gemm<64,64><<<dim3(NTOT/128, 1), 256, GEMM2_SMEM>>>(bufA, g2W, bufB, 256);
    gat_agg_fused<1,64,true,false><<<NG, 512, AGG2_SMEM>>>(
        bufB, nullptr, nullptr, g2as, g2ad, g2b, bufA);

    // 5) precompute x-part of gates (batch-amortized Wih reads)
    gx_kernel<<<2*TT, 256>>>(Wih_f, bih_f, bhh_f, Wih_b, bih_b, bhh_b);

    // 6) cluster-resident BiLSTM: 8 chains x 8-CTA clusters, W in registers
    lstm_kernel<<<64, 256>>>(Whh_f, Whh_b);

    // 7) heads + Poincare projection
    head_kernel<<<BSZ, LD>>>(muW, mub, lvW, lvb, out);
}